// round 5
// baseline (speedup 1.0000x reference)
#include <cuda_runtime.h>
#include <math.h>

#define E_TILE   128
#define THREADS  256
#define HID      64
#define IN_CH    16
#define OUT_CH   16
#define PED      6
#define RS       260        // row stride (floats) for duplicated activation tiles

typedef unsigned long long ull;

__device__ int g_ei_is64;   // 1 if edge_index is int64 (little-endian lo/hi pairs)

struct Smem {
    float W1[PED][HID];          // 1536 B
    float b1[HID];               // 256
    float Wh[HID][HID];          // 16384
    float bh[HID];               // 256
    float WoT[HID][256];         // 65536, layout [k][og*32 + i*2 + c]
    float bo[256];               // 1024
    float PE[PED][E_TILE];       // 3072
    float X[IN_CH][E_TILE];      // 8192
    float H1d[HID][RS];          // 66560, duplicated: [k][2e]==[k][2e+1]==H1[k][e]
    float H2d[HID][RS];          // 66560
    int   dst[E_TILE];           // 512     => total 229888 B
};

__device__ __forceinline__ float gelu_exact(float v) {
    return 0.5f * v * (1.0f + erff(v * 0.70710678118654752440f));
}

__device__ __forceinline__ ull pack2(float a, float b) {
    ull r; asm("mov.b64 %0, {%1, %2};" : "=l"(r) : "f"(a), "f"(b)); return r;
}
__device__ __forceinline__ void unpack2(ull v, float& a, float& b) {
    asm("mov.b64 {%0, %1}, %2;" : "=f"(a), "=f"(b) : "l"(v));
}
__device__ __forceinline__ ull fma2(ull a, ull b, ull c) {
    ull d; asm("fma.rn.f32x2 %0, %1, %2, %3;" : "=l"(d) : "l"(a), "l"(b), "l"(c)); return d;
}
__device__ __forceinline__ ull add2(ull a, ull b) {
    ull d; asm("add.rn.f32x2 %0, %1, %2;" : "=l"(d) : "l"(a), "l"(b)); return d;
}

__global__ void detect_dtype_kernel(const unsigned* __restrict__ w) {
    int all0 = 1;
    #pragma unroll
    for (int i = 1; i < 128; i += 2) all0 &= (w[i] == 0u);
    g_ei_is64 = all0;
}

__global__ void zero_kernel(float* out, int n) {
    int i = blockIdx.x * blockDim.x + threadIdx.x;
    if (i < n) out[i] = 0.0f;
}

__global__ __launch_bounds__(THREADS, 1)
void integral_transform_kernel(
    const float* __restrict__ x,
    const float* __restrict__ pos,
    const int* __restrict__ ei,
    const float* __restrict__ gW1, const float* __restrict__ gb1,
    const float* __restrict__ gWh, const float* __restrict__ gbh,
    const float* __restrict__ gWo, const float* __restrict__ gbo,
    float* __restrict__ out,
    int E)
{
    extern __shared__ char smem_raw[];
    Smem* sm = reinterpret_cast<Smem*>(smem_raw);

    const int tid = threadIdx.x;
    const int eg  = tid >> 3;   // 0..31 (4 edges each)
    const int og  = tid & 7;    // 0..7  (output-column group)

    // ---------------- Stage 0: weights + gathers ----------------
    {
        const float4* s; float4* d;
        s = (const float4*)gW1; d = (float4*)&sm->W1[0][0];
        for (int i = tid; i < (PED * HID) / 4; i += THREADS) d[i] = s[i];
        s = (const float4*)gb1; d = (float4*)&sm->b1[0];
        for (int i = tid; i < HID / 4; i += THREADS) d[i] = s[i];
        s = (const float4*)gWh; d = (float4*)&sm->Wh[0][0];
        for (int i = tid; i < (HID * HID) / 4; i += THREADS) d[i] = s[i];
        s = (const float4*)gbh; d = (float4*)&sm->bh[0];
        for (int i = tid; i < HID / 4; i += THREADS) d[i] = s[i];
        s = (const float4*)gbo; d = (float4*)&sm->bo[0];
        for (int i = tid; i < 256 / 4; i += THREADS) d[i] = s[i];
        // Wo transposed: [k][og*32 + i*2 + c]  (c = o&1, og = o>>1)
        for (int n = tid; n < HID * 256; n += THREADS) {
            int k = n >> 8, col = n & 255;
            int i = col >> 4, o = col & 15;
            sm->WoT[k][(o >> 1) * 32 + i * 2 + (o & 1)] = gWo[n];
        }
    }

    const int base = blockIdx.x * E_TILE;
    if (tid < E_TILE) {
        int ge = base + tid;
        bool valid = ge < E;
        int idx = valid ? ge : 0;
        int s, dd;
        if (g_ei_is64) { s = ei[2 * idx];  dd = ei[2 * (E + idx)]; }
        else           { s = ei[idx];      dd = ei[E + idx]; }
        sm->dst[tid] = valid ? dd : -1;
        sm->PE[0][tid] = pos[s * 3 + 0];
        sm->PE[1][tid] = pos[s * 3 + 1];
        sm->PE[2][tid] = pos[s * 3 + 2];
        sm->PE[3][tid] = pos[dd * 3 + 0];
        sm->PE[4][tid] = pos[dd * 3 + 1];
        sm->PE[5][tid] = pos[dd * 3 + 2];
        #pragma unroll
        for (int i = 0; i < IN_CH; ++i)
            sm->X[i][tid] = x[s * IN_CH + i];
    }
    __syncthreads();

    // ---------------- Stage 1: H1 = gelu(PE @ W1 + b1) (scalar, tiny) -------
    {
        float acc[4][8];
        #pragma unroll
        for (int e = 0; e < 4; ++e)
            #pragma unroll
            for (int j = 0; j < 8; ++j) acc[e][j] = 0.0f;

        #pragma unroll
        for (int k = 0; k < PED; ++k) {
            float4 h = *(const float4*)&sm->PE[k][eg * 4];
            float he[4] = {h.x, h.y, h.z, h.w};
            float w[8];
            *(float4*)&w[0] = *(const float4*)&sm->W1[k][og * 8];
            *(float4*)&w[4] = *(const float4*)&sm->W1[k][og * 8 + 4];
            #pragma unroll
            for (int j = 0; j < 8; ++j)
                #pragma unroll
                for (int e = 0; e < 4; ++e)
                    acc[e][j] += he[e] * w[j];
        }
        #pragma unroll
        for (int j = 0; j < 8; ++j) {
            float b = sm->b1[og * 8 + j];
            float g0 = gelu_exact(acc[0][j] + b);
            float g1 = gelu_exact(acc[1][j] + b);
            float g2 = gelu_exact(acc[2][j] + b);
            float g3 = gelu_exact(acc[3][j] + b);
            ulonglong2* p = (ulonglong2*)&sm->H1d[og * 8 + j][eg * 8];
            ulonglong2 v0; v0.x = pack2(g0, g0); v0.y = pack2(g1, g1);
            ulonglong2 v1; v1.x = pack2(g2, g2); v1.y = pack2(g3, g3);
            p[0] = v0; p[1] = v1;
        }
    }
    __syncthreads();

    // ---------------- Stage 2: H2 = gelu(H1 @ Wh + bh)  (f32x2) -------------
    {
        ull acc2[4][4];   // [e][jpair], pair = (j=2jp, j=2jp+1)
        #pragma unroll
        for (int e = 0; e < 4; ++e)
            #pragma unroll
            for (int jp = 0; jp < 4; ++jp) acc2[e][jp] = 0ULL;

        #pragma unroll 4
        for (int k = 0; k < HID; ++k) {
            const ulonglong2* hp = (const ulonglong2*)&sm->H1d[k][eg * 8];
            ulonglong2 hA = hp[0], hB = hp[1];           // (h0,h0),(h1,h1),(h2,h2),(h3,h3)
            const ulonglong2* wp = (const ulonglong2*)&sm->Wh[k][og * 8];
            ulonglong2 wA = wp[0], wB = wp[1];           // (w0,w1),(w2,w3),(w4,w5),(w6,w7)
            #pragma unroll
            for (int e = 0; e < 4; ++e) {
                ull hd = (e == 0) ? hA.x : (e == 1) ? hA.y : (e == 2) ? hB.x : hB.y;
                acc2[e][0] = fma2(hd, wA.x, acc2[e][0]);
                acc2[e][1] = fma2(hd, wA.y, acc2[e][1]);
                acc2[e][2] = fma2(hd, wB.x, acc2[e][2]);
                acc2[e][3] = fma2(hd, wB.y, acc2[e][3]);
            }
        }

        float v[8][4];    // [j][e]
        #pragma unroll
        for (int jp = 0; jp < 4; ++jp)
            #pragma unroll
            for (int e = 0; e < 4; ++e)
                unpack2(acc2[e][jp], v[2 * jp][e], v[2 * jp + 1][e]);

        #pragma unroll
        for (int j = 0; j < 8; ++j) {
            float b = sm->bh[og * 8 + j];
            float g0 = gelu_exact(v[j][0] + b);
            float g1 = gelu_exact(v[j][1] + b);
            float g2 = gelu_exact(v[j][2] + b);
            float g3 = gelu_exact(v[j][3] + b);
            ulonglong2* p = (ulonglong2*)&sm->H2d[og * 8 + j][eg * 8];
            ulonglong2 w0; w0.x = pack2(g0, g0); w0.y = pack2(g1, g1);
            ulonglong2 w1; w1.x = pack2(g2, g2); w1.y = pack2(g3, g3);
            p[0] = w0; p[1] = w1;
        }
    }
    __syncthreads();

    // ---------------- Stage 3: C = H2 @ Wo (+bo), msg = x·C, scatter (f32x2) --
    // acc2[e][i] = pair (C[e, i*16+og*2], C[e, i*16+og*2+1]); i-contraction local.
    {
        ull acc2[4][16];
        #pragma unroll
        for (int e = 0; e < 4; ++e)
            #pragma unroll
            for (int i = 0; i < 16; ++i) acc2[e][i] = 0ULL;

        #pragma unroll 1
        for (int k = 0; k < HID; ++k) {
            const ulonglong2* hp = (const ulonglong2*)&sm->H2d[k][eg * 8];
            ulonglong2 hA = hp[0], hB = hp[1];
            ull hd0 = hA.x, hd1 = hA.y, hd2 = hB.x, hd3 = hB.y;
            const ulonglong2* wp = (const ulonglong2*)&sm->WoT[k][og * 32];
            #pragma unroll
            for (int ic = 0; ic < 8; ++ic) {
                ulonglong2 w2 = wp[ic];       // pairs for i=2ic, i=2ic+1
                acc2[0][2 * ic]     = fma2(hd0, w2.x, acc2[0][2 * ic]);
                acc2[1][2 * ic]     = fma2(hd1, w2.x, acc2[1][2 * ic]);
                acc2[2][2 * ic]     = fma2(hd2, w2.x, acc2[2][2 * ic]);
                acc2[3][2 * ic]     = fma2(hd3, w2.x, acc2[3][2 * ic]);
                acc2[0][2 * ic + 1] = fma2(hd0, w2.y, acc2[0][2 * ic + 1]);
                acc2[1][2 * ic + 1] = fma2(hd1, w2.y, acc2[1][2 * ic + 1]);
                acc2[2][2 * ic + 1] = fma2(hd2, w2.y, acc2[2][2 * ic + 1]);
                acc2[3][2 * ic + 1] = fma2(hd3, w2.y, acc2[3][2 * ic + 1]);
            }
        }

        #pragma unroll
        for (int e = 0; e < 4; ++e) {
            int eabs = eg * 4 + e;
            int d = sm->dst[eabs];
            ull m = 0ULL;
            #pragma unroll
            for (int i = 0; i < 16; ++i) {
                ull bo2 = *(const ull*)&sm->bo[i * 16 + og * 2];
                float xv = sm->X[i][eabs];
                ull xd = pack2(xv, xv);
                m = fma2(xd, add2(acc2[e][i], bo2), m);
            }
            float m0, m1;
            unpack2(m, m0, m1);
            if (d >= 0) {
                atomicAdd(&out[d * OUT_CH + og * 2 + 0], m0);
                atomicAdd(&out[d * OUT_CH + og * 2 + 1], m1);
            }
        }
    }
}

extern "C" void kernel_launch(void* const* d_in, const int* in_sizes, int n_in,
                              void* d_out, int out_size) {
    const float* x   = (const float*)d_in[0];
    const float* pos = (const float*)d_in[1];
    const int*   ei  = (const int*)d_in[2];
    const float* W1  = (const float*)d_in[3];
    const float* b1  = (const float*)d_in[4];
    const float* Wh  = (const float*)d_in[5];
    const float* bh  = (const float*)d_in[6];
    const float* Wo  = (const float*)d_in[7];
    const float* bo  = (const float*)d_in[8];
    float*       out = (float*)d_out;

    int E = in_sizes[2] / 2;

    cudaFuncSetAttribute(integral_transform_kernel,
                         cudaFuncAttributeMaxDynamicSharedMemorySize,
                         (int)sizeof(Smem));

    detect_dtype_kernel<<<1, 1>>>((const unsigned*)ei);
    zero_kernel<<<(out_size + 255) / 256, 256>>>(out, out_size);

    int blocks = (E + E_TILE - 1) / E_TILE;
    integral_transform_kernel<<<blocks, THREADS, sizeof(Smem)>>>(
        x, pos, ei, W1, b1, Wh, bh, Wo, bo, out, E);
}

// round 13
// speedup vs baseline: 6.6961x; 6.6961x over previous
#include <cuda_runtime.h>
#include <math.h>

#define THREADS   256
#define E_TILE    128
#define HID       64
#define IN_CH     16
#define OUT_CH    16
#define PED       6
#define HPAD      132
#define MAXN      50000
#define GROW      65            // 64 H2-rows + 1 bias row
#define GSTRIDE   (GROW * 16)   // 1040 floats per node

__device__ int g_ei_is64;
__device__ static float g_G[(size_t)MAXN * GSTRIDE];   // 208 MB scratch

struct Smem {
    float W1[PED][HID];
    float b1[HID];
    float Wh[HID][HID];
    float bh[HID];
    float PE[PED][E_TILE];
    float H1[HID][HPAD];
    float H2[HID][HPAD];
    int   src[E_TILE];
    int   dst[E_TILE];
};

__device__ __forceinline__ float gelu_exact(float v) {
    return 0.5f * v * (1.0f + erff(v * 0.70710678118654752440f));
}

__global__ void detect_dtype_kernel(const unsigned* __restrict__ w) {
    int all0 = 1;
    #pragma unroll
    for (int i = 1; i < 128; i += 2) all0 &= (w[i] == 0u);
    g_ei_is64 = all0;
}

__global__ void zero_kernel(float* out, int n) {
    int i = blockIdx.x * blockDim.x + threadIdx.x;
    if (i < n) out[i] = 0.0f;
}

// ---------- G precompute: G[s][k][o] = sum_i Wo[k][i*16+o] * x[s][i]; row 64 = bias row
#define GK_NODES 16
#define WPAD     20
__global__ __launch_bounds__(256)
void g_precompute_kernel(const float* __restrict__ x,
                         const float* __restrict__ gWo,
                         const float* __restrict__ gbo,
                         int n_points)
{
    extern __shared__ float ws[];               // WoT[64][16][WPAD] + boT[16][WPAD]
    float* WoT = ws;                            // [k][o][i] padded
    float* boT = ws + 64 * 16 * WPAD;

    int tid = threadIdx.x;
    for (int n = tid; n < 64 * 256; n += 256) {
        int k = n >> 8, c = n & 255;
        int i = c >> 4, o = c & 15;
        WoT[(k * 16 + o) * WPAD + i] = gWo[n];
    }
    for (int n = tid; n < 256; n += 256) {
        int i = n >> 4, o = n & 15;
        boT[o * WPAD + i] = gbo[n];
    }
    __syncthreads();

    int node = blockIdx.x * GK_NODES + (tid >> 4);
    int o = tid & 15;
    if (node >= n_points) return;

    float xr[16];
    const float4* xp = (const float4*)(x + (size_t)node * 16);
    *(float4*)&xr[0]  = xp[0];
    *(float4*)&xr[4]  = xp[1];
    *(float4*)&xr[8]  = xp[2];
    *(float4*)&xr[12] = xp[3];

    float* gout = g_G + (size_t)node * GSTRIDE + o;
    #pragma unroll 4
    for (int k = 0; k < 64; ++k) {
        const float* wr = &WoT[(k * 16 + o) * WPAD];
        float acc = 0.0f;
        #pragma unroll
        for (int i = 0; i < 16; ++i) acc += wr[i] * xr[i];
        gout[k * 16] = acc;
    }
    {
        const float* br = &boT[o * WPAD];
        float acc = 0.0f;
        #pragma unroll
        for (int i = 0; i < 16; ++i) acc += br[i] * xr[i];
        gout[64 * 16] = acc;
    }
}

// ---------- main edge kernel ----------
__global__ __launch_bounds__(THREADS, 2)
void integral_transform_kernel(
    const float* __restrict__ pos,
    const int* __restrict__ ei,
    const float* __restrict__ gW1, const float* __restrict__ gb1,
    const float* __restrict__ gWh, const float* __restrict__ gbh,
    float* __restrict__ out,
    int E)
{
    extern __shared__ char smem_raw[];
    Smem* sm = reinterpret_cast<Smem*>(smem_raw);

    const int tid = threadIdx.x;
    const int eg  = tid >> 3;   // 0..31 (4 edges each)
    const int og  = tid & 7;    // 0..7

    // ---- Stage 0: weights + gathers ----
    {
        const float4* s; float4* d;
        s = (const float4*)gW1; d = (float4*)&sm->W1[0][0];
        for (int i = tid; i < (PED * HID) / 4; i += THREADS) d[i] = s[i];
        s = (const float4*)gb1; d = (float4*)&sm->b1[0];
        for (int i = tid; i < HID / 4; i += THREADS) d[i] = s[i];
        s = (const float4*)gWh; d = (float4*)&sm->Wh[0][0];
        for (int i = tid; i < (HID * HID) / 4; i += THREADS) d[i] = s[i];
        s = (const float4*)gbh; d = (float4*)&sm->bh[0];
        for (int i = tid; i < HID / 4; i += THREADS) d[i] = s[i];
    }

    const int base = blockIdx.x * E_TILE;
    if (tid < E_TILE) {
        int ge = base + tid;
        bool valid = ge < E;
        int idx = valid ? ge : 0;
        int s, dd;
        if (g_ei_is64) { s = ei[2 * idx];  dd = ei[2 * (E + idx)]; }
        else           { s = ei[idx];      dd = ei[E + idx]; }
        sm->src[tid] = s;
        sm->dst[tid] = valid ? dd : -1;
        sm->PE[0][tid] = pos[s * 3 + 0];
        sm->PE[1][tid] = pos[s * 3 + 1];
        sm->PE[2][tid] = pos[s * 3 + 2];
        sm->PE[3][tid] = pos[dd * 3 + 0];
        sm->PE[4][tid] = pos[dd * 3 + 1];
        sm->PE[5][tid] = pos[dd * 3 + 2];
    }
    __syncthreads();

    // ---- Stage 1: H1 = gelu(PE @ W1 + b1) ----
    {
        float acc[4][8];
        #pragma unroll
        for (int e = 0; e < 4; ++e)
            #pragma unroll
            for (int j = 0; j < 8; ++j) acc[e][j] = 0.0f;

        #pragma unroll
        for (int k = 0; k < PED; ++k) {
            float4 h = *(const float4*)&sm->PE[k][eg * 4];
            float he[4] = {h.x, h.y, h.z, h.w};
            float w[8];
            *(float4*)&w[0] = *(const float4*)&sm->W1[k][og * 8];
            *(float4*)&w[4] = *(const float4*)&sm->W1[k][og * 8 + 4];
            #pragma unroll
            for (int j = 0; j < 8; ++j)
                #pragma unroll
                for (int e = 0; e < 4; ++e)
                    acc[e][j] += he[e] * w[j];
        }
        #pragma unroll
        for (int j = 0; j < 8; ++j) {
            float b = sm->b1[og * 8 + j];
            float4 v;
            v.x = gelu_exact(acc[0][j] + b);
            v.y = gelu_exact(acc[1][j] + b);
            v.z = gelu_exact(acc[2][j] + b);
            v.w = gelu_exact(acc[3][j] + b);
            *(float4*)&sm->H1[og * 8 + j][eg * 4] = v;
        }
    }
    __syncthreads();

    // ---- Stage 2: H2 = gelu(H1 @ Wh + bh) ----
    {
        float acc[4][8];
        #pragma unroll
        for (int e = 0; e < 4; ++e)
            #pragma unroll
            for (int j = 0; j < 8; ++j) acc[e][j] = 0.0f;

        #pragma unroll 4
        for (int k = 0; k < HID; ++k) {
            float4 h = *(const float4*)&sm->H1[k][eg * 4];
            float he[4] = {h.x, h.y, h.z, h.w};
            float w[8];
            *(float4*)&w[0] = *(const float4*)&sm->Wh[k][og * 8];
            *(float4*)&w[4] = *(const float4*)&sm->Wh[k][og * 8 + 4];
            #pragma unroll
            for (int j = 0; j < 8; ++j)
                #pragma unroll
                for (int e = 0; e < 4; ++e)
                    acc[e][j] += he[e] * w[j];
        }
        #pragma unroll
        for (int j = 0; j < 8; ++j) {
            float b = sm->bh[og * 8 + j];
            float4 v;
            v.x = gelu_exact(acc[0][j] + b);
            v.y = gelu_exact(acc[1][j] + b);
            v.z = gelu_exact(acc[2][j] + b);
            v.w = gelu_exact(acc[3][j] + b);
            *(float4*)&sm->H2[og * 8 + j][eg * 4] = v;
        }
    }
    __syncthreads();

    // ---- Stage 3: msg[e,o] = sum_k H2[e,k] * G[src][k][o] + G[src][64][o] ----
    {
        float2 acc[4];
        #pragma unroll
        for (int e = 0; e < 4; ++e) { acc[e].x = 0.0f; acc[e].y = 0.0f; }

        const float* gp[4];
        #pragma unroll
        for (int e = 0; e < 4; ++e)
            gp[e] = g_G + (size_t)sm->src[eg * 4 + e] * GSTRIDE + og * 2;

        #pragma unroll 8
        for (int k = 0; k < HID; ++k) {
            float4 h4 = *(const float4*)&sm->H2[k][eg * 4];
            float he[4] = {h4.x, h4.y, h4.z, h4.w};
            #pragma unroll
            for (int e = 0; e < 4; ++e) {
                float2 g = *(const float2*)(gp[e] + k * 16);
                acc[e].x += he[e] * g.x;
                acc[e].y += he[e] * g.y;
            }
        }

        #pragma unroll
        for (int e = 0; e < 4; ++e) {
            int d = sm->dst[eg * 4 + e];
            float2 gb = *(const float2*)(gp[e] + 64 * 16);
            float m0 = acc[e].x + gb.x;
            float m1 = acc[e].y + gb.y;
            if (d >= 0) {
                atomicAdd(&out[(size_t)d * OUT_CH + og * 2 + 0], m0);
                atomicAdd(&out[(size_t)d * OUT_CH + og * 2 + 1], m1);
            }
        }
    }
}

extern "C" void kernel_launch(void* const* d_in, const int* in_sizes, int n_in,
                              void* d_out, int out_size) {
    const float* x   = (const float*)d_in[0];
    const float* pos = (const float*)d_in[1];
    const int*   ei  = (const int*)d_in[2];
    const float* W1  = (const float*)d_in[3];
    const float* b1  = (const float*)d_in[4];
    const float* Wh  = (const float*)d_in[5];
    const float* bh  = (const float*)d_in[6];
    const float* Wo  = (const float*)d_in[7];
    const float* bo  = (const float*)d_in[8];
    float*       out = (float*)d_out;

    int E        = in_sizes[2] / 2;
    int n_points = in_sizes[0] / IN_CH;
    if (n_points > MAXN) n_points = MAXN;

    cudaFuncSetAttribute(integral_transform_kernel,
                         cudaFuncAttributeMaxDynamicSharedMemorySize,
                         (int)sizeof(Smem));
    int gsmem = (64 * 16 * WPAD + 16 * WPAD) * (int)sizeof(float);
    cudaFuncSetAttribute(g_precompute_kernel,
                         cudaFuncAttributeMaxDynamicSharedMemorySize, gsmem);

    detect_dtype_kernel<<<1, 1>>>((const unsigned*)ei);
    zero_kernel<<<(out_size + 255) / 256, 256>>>(out, out_size);
    g_precompute_kernel<<<(n_points + GK_NODES - 1) / GK_NODES, 256, gsmem>>>(
        x, Wo, bo, n_points);

    int blocks = (E + E_TILE - 1) / E_TILE;
    integral_transform_kernel<<<blocks, THREADS, sizeof(Smem)>>>(
        pos, ei, W1, b1, Wh, bh, out, E);
}

// round 14
// speedup vs baseline: 7.1583x; 1.0690x over previous
#include <cuda_runtime.h>
#include <math.h>

#define THREADS   256
#define E_TILE    128
#define HID       64
#define IN_CH     16
#define OUT_CH    16
#define PED       6
#define HPAD      132
#define MAXN      50000
#define MAXE      1000000
#define GROW      65            // 64 H2-rows + 1 bias row
#define GSTRIDE   (GROW * 16)   // 1040 floats per node

__device__ int g_ei_is64;
__device__ static float g_G[(size_t)MAXN * GSTRIDE];   // 208 MB scratch
__device__ static int   g_perm[MAXE];
__device__ static int   g_cnt[MAXN + 1];

struct Smem {
    float W1[PED][HID];
    float b1[HID];
    float Wh[HID][HID];
    float bh[HID];
    float PE[PED][E_TILE];
    float H1[HID][HPAD];
    float H2[HID][HPAD];
    int   src[E_TILE];
    int   dst[E_TILE];
};

__device__ __forceinline__ float gelu_exact(float v) {
    return 0.5f * v * (1.0f + erff(v * 0.70710678118654752440f));
}

__global__ void detect_dtype_kernel(const unsigned* __restrict__ w) {
    int all0 = 1;
    #pragma unroll
    for (int i = 1; i < 128; i += 2) all0 &= (w[i] == 0u);
    g_ei_is64 = all0;
}

__global__ void zero_kernel(float* out, int n) {
    int i = blockIdx.x * blockDim.x + threadIdx.x;
    if (i < n) out[i] = 0.0f;
}

__global__ void zero_cnt_kernel(int n) {
    int i = blockIdx.x * blockDim.x + threadIdx.x;
    if (i < n) g_cnt[i] = 0;
}

// ---------- counting sort by src ----------
__global__ void hist_kernel(const int* __restrict__ ei, int E) {
    int e = blockIdx.x * blockDim.x + threadIdx.x;
    if (e < E) {
        int s = g_ei_is64 ? ei[2 * e] : ei[e];
        atomicAdd(&g_cnt[s], 1);
    }
}

// single-CTA two-level exclusive scan of g_cnt[0..n)
__global__ void scan_kernel(int n) {
    __shared__ int part[1024];
    int tid = threadIdx.x;
    int chunk = (n + 1023) / 1024;
    int beg = tid * chunk;
    int end = beg + chunk; if (end > n) end = n;
    int sum = 0;
    for (int i = beg; i < end; ++i) sum += g_cnt[i];
    part[tid] = sum;
    __syncthreads();
    for (int off = 1; off < 1024; off <<= 1) {
        int v = (tid >= off) ? part[tid - off] : 0;
        __syncthreads();
        part[tid] += v;
        __syncthreads();
    }
    int run = part[tid] - sum;      // exclusive prefix of this chunk
    for (int i = beg; i < end; ++i) {
        int c = g_cnt[i];
        g_cnt[i] = run;
        run += c;
    }
}

__global__ void scatter_kernel(const int* __restrict__ ei, int E) {
    int e = blockIdx.x * blockDim.x + threadIdx.x;
    if (e < E) {
        int s = g_ei_is64 ? ei[2 * e] : ei[e];
        int pos = atomicAdd(&g_cnt[s], 1);
        g_perm[pos] = e;
    }
}

// ---------- G precompute: G[s][k][o] = sum_i Wo[k][i*16+o] * x[s][i]; row 64 = bias row
#define GK_NODES 16
#define WPAD     20
__global__ __launch_bounds__(256)
void g_precompute_kernel(const float* __restrict__ x,
                         const float* __restrict__ gWo,
                         const float* __restrict__ gbo,
                         int n_points)
{
    extern __shared__ float ws[];
    float* WoT = ws;                            // [k][o][i] padded
    float* boT = ws + 64 * 16 * WPAD;

    int tid = threadIdx.x;
    for (int n = tid; n < 64 * 256; n += 256) {
        int k = n >> 8, c = n & 255;
        int i = c >> 4, o = c & 15;
        WoT[(k * 16 + o) * WPAD + i] = gWo[n];
    }
    for (int n = tid; n < 256; n += 256) {
        int i = n >> 4, o = n & 15;
        boT[o * WPAD + i] = gbo[n];
    }
    __syncthreads();

    int node = blockIdx.x * GK_NODES + (tid >> 4);
    int o = tid & 15;
    if (node >= n_points) return;

    float xr[16];
    const float4* xp = (const float4*)(x + (size_t)node * 16);
    *(float4*)&xr[0]  = xp[0];
    *(float4*)&xr[4]  = xp[1];
    *(float4*)&xr[8]  = xp[2];
    *(float4*)&xr[12] = xp[3];

    float* gout = g_G + (size_t)node * GSTRIDE + o;
    #pragma unroll 4
    for (int k = 0; k < 64; ++k) {
        const float* wr = &WoT[(k * 16 + o) * WPAD];
        float acc = 0.0f;
        #pragma unroll
        for (int i = 0; i < 16; ++i) acc += wr[i] * xr[i];
        gout[k * 16] = acc;
    }
    {
        const float* br = &boT[o * WPAD];
        float acc = 0.0f;
        #pragma unroll
        for (int i = 0; i < 16; ++i) acc += br[i] * xr[i];
        gout[64 * 16] = acc;
    }
}

// ---------- main edge kernel (src-sorted via g_perm) ----------
__global__ __launch_bounds__(THREADS, 2)
void integral_transform_kernel(
    const float* __restrict__ pos,
    const int* __restrict__ ei,
    const float* __restrict__ gW1, const float* __restrict__ gb1,
    const float* __restrict__ gWh, const float* __restrict__ gbh,
    float* __restrict__ out,
    int E)
{
    extern __shared__ char smem_raw[];
    Smem* sm = reinterpret_cast<Smem*>(smem_raw);

    const int tid = threadIdx.x;
    const int eg  = tid >> 3;   // 0..31 (4 edges each)
    const int og  = tid & 7;    // 0..7

    // ---- Stage 0: weights + gathers ----
    {
        const float4* s; float4* d;
        s = (const float4*)gW1; d = (float4*)&sm->W1[0][0];
        for (int i = tid; i < (PED * HID) / 4; i += THREADS) d[i] = s[i];
        s = (const float4*)gb1; d = (float4*)&sm->b1[0];
        for (int i = tid; i < HID / 4; i += THREADS) d[i] = s[i];
        s = (const float4*)gWh; d = (float4*)&sm->Wh[0][0];
        for (int i = tid; i < (HID * HID) / 4; i += THREADS) d[i] = s[i];
        s = (const float4*)gbh; d = (float4*)&sm->bh[0];
        for (int i = tid; i < HID / 4; i += THREADS) d[i] = s[i];
    }

    const int base = blockIdx.x * E_TILE;
    if (tid < E_TILE) {
        int ge = base + tid;
        bool valid = ge < E;
        int pe = valid ? g_perm[ge] : 0;
        int s, dd;
        if (g_ei_is64) { s = ei[2 * pe];  dd = ei[2 * (E + pe)]; }
        else           { s = ei[pe];      dd = ei[E + pe]; }
        sm->src[tid] = s;
        sm->dst[tid] = valid ? dd : -1;
        sm->PE[0][tid] = pos[s * 3 + 0];
        sm->PE[1][tid] = pos[s * 3 + 1];
        sm->PE[2][tid] = pos[s * 3 + 2];
        sm->PE[3][tid] = pos[dd * 3 + 0];
        sm->PE[4][tid] = pos[dd * 3 + 1];
        sm->PE[5][tid] = pos[dd * 3 + 2];
    }
    __syncthreads();

    // ---- Stage 1: H1 = gelu(PE @ W1 + b1) ----
    {
        float acc[4][8];
        #pragma unroll
        for (int e = 0; e < 4; ++e)
            #pragma unroll
            for (int j = 0; j < 8; ++j) acc[e][j] = 0.0f;

        #pragma unroll
        for (int k = 0; k < PED; ++k) {
            float4 h = *(const float4*)&sm->PE[k][eg * 4];
            float he[4] = {h.x, h.y, h.z, h.w};
            float w[8];
            *(float4*)&w[0] = *(const float4*)&sm->W1[k][og * 8];
            *(float4*)&w[4] = *(const float4*)&sm->W1[k][og * 8 + 4];
            #pragma unroll
            for (int j = 0; j < 8; ++j)
                #pragma unroll
                for (int e = 0; e < 4; ++e)
                    acc[e][j] += he[e] * w[j];
        }
        #pragma unroll
        for (int j = 0; j < 8; ++j) {
            float b = sm->b1[og * 8 + j];
            float4 v;
            v.x = gelu_exact(acc[0][j] + b);
            v.y = gelu_exact(acc[1][j] + b);
            v.z = gelu_exact(acc[2][j] + b);
            v.w = gelu_exact(acc[3][j] + b);
            *(float4*)&sm->H1[og * 8 + j][eg * 4] = v;
        }
    }
    __syncthreads();

    // ---- Stage 2: H2 = gelu(H1 @ Wh + bh) ----
    {
        float acc[4][8];
        #pragma unroll
        for (int e = 0; e < 4; ++e)
            #pragma unroll
            for (int j = 0; j < 8; ++j) acc[e][j] = 0.0f;

        #pragma unroll 4
        for (int k = 0; k < HID; ++k) {
            float4 h = *(const float4*)&sm->H1[k][eg * 4];
            float he[4] = {h.x, h.y, h.z, h.w};
            float w[8];
            *(float4*)&w[0] = *(const float4*)&sm->Wh[k][og * 8];
            *(float4*)&w[4] = *(const float4*)&sm->Wh[k][og * 8 + 4];
            #pragma unroll
            for (int j = 0; j < 8; ++j)
                #pragma unroll
                for (int e = 0; e < 4; ++e)
                    acc[e][j] += he[e] * w[j];
        }
        #pragma unroll
        for (int j = 0; j < 8; ++j) {
            float b = sm->bh[og * 8 + j];
            float4 v;
            v.x = gelu_exact(acc[0][j] + b);
            v.y = gelu_exact(acc[1][j] + b);
            v.z = gelu_exact(acc[2][j] + b);
            v.w = gelu_exact(acc[3][j] + b);
            *(float4*)&sm->H2[og * 8 + j][eg * 4] = v;
        }
    }
    __syncthreads();

    // ---- Stage 3: warp-per-edge coalesced G-contraction ----
    // lane l: float4 #(32*i + l) of G row -> k = 8i + (l>>2), o = 4*(l&3)..+3
    {
        const int wrp  = tid >> 5;        // 0..7, handles edges wrp*16..+15
        const int lane = tid & 31;
        const int kq   = lane >> 2;       // k-partition 0..7
        #pragma unroll 1
        for (int n = 0; n < 16; ++n) {
            int eabs = wrp * 16 + n;
            int s = sm->src[eabs];
            const float4* grow = (const float4*)(g_G + (size_t)s * GSTRIDE);
            float m0 = 0.0f, m1 = 0.0f, m2 = 0.0f, m3 = 0.0f;
            #pragma unroll
            for (int i = 0; i < 8; ++i) {
                float4 g = grow[i * 32 + lane];
                float h = sm->H2[i * 8 + kq][eabs];
                m0 += h * g.x; m1 += h * g.y; m2 += h * g.z; m3 += h * g.w;
            }
            #pragma unroll
            for (int off = 4; off <= 16; off <<= 1) {
                m0 += __shfl_xor_sync(0xFFFFFFFFu, m0, off);
                m1 += __shfl_xor_sync(0xFFFFFFFFu, m1, off);
                m2 += __shfl_xor_sync(0xFFFFFFFFu, m2, off);
                m3 += __shfl_xor_sync(0xFFFFFFFFu, m3, off);
            }
            if (lane < 4) {
                int d = sm->dst[eabs];
                if (d >= 0) {
                    float4 gb = grow[256 + lane];   // bias row, o = 4*lane..+3
                    float* op = &out[(size_t)d * OUT_CH + 4 * lane];
                    atomicAdd(op + 0, m0 + gb.x);
                    atomicAdd(op + 1, m1 + gb.y);
                    atomicAdd(op + 2, m2 + gb.z);
                    atomicAdd(op + 3, m3 + gb.w);
                }
            }
        }
    }
}

extern "C" void kernel_launch(void* const* d_in, const int* in_sizes, int n_in,
                              void* d_out, int out_size) {
    const float* x   = (const float*)d_in[0];
    const float* pos = (const float*)d_in[1];
    const int*   ei  = (const int*)d_in[2];
    const float* W1  = (const float*)d_in[3];
    const float* b1  = (const float*)d_in[4];
    const float* Wh  = (const float*)d_in[5];
    const float* bh  = (const float*)d_in[6];
    const float* Wo  = (const float*)d_in[7];
    const float* bo  = (const float*)d_in[8];
    float*       out = (float*)d_out;

    int E        = in_sizes[2] / 2;
    int n_points = in_sizes[0] / IN_CH;
    if (n_points > MAXN) n_points = MAXN;
    if (E > MAXE) E = MAXE;

    cudaFuncSetAttribute(integral_transform_kernel,
                         cudaFuncAttributeMaxDynamicSharedMemorySize,
                         (int)sizeof(Smem));
    int gsmem = (64 * 16 * WPAD + 16 * WPAD) * (int)sizeof(float);
    cudaFuncSetAttribute(g_precompute_kernel,
                         cudaFuncAttributeMaxDynamicSharedMemorySize, gsmem);

    detect_dtype_kernel<<<1, 1>>>((const unsigned*)ei);
    zero_kernel<<<(out_size + 255) / 256, 256>>>(out, out_size);
    zero_cnt_kernel<<<(n_points + 256) / 256, 256>>>(n_points + 1);
    hist_kernel<<<(E + 255) / 256, 256>>>(ei, E);
    scan_kernel<<<1, 1024>>>(n_points);
    scatter_kernel<<<(E + 255) / 256, 256>>>(ei, E);
    g_precompute_kernel<<<(n_points + GK_NODES - 1) / GK_NODES, 256, gsmem>>>(
        x, Wo, bo, n_points);

    int blocks = (E + E_TILE - 1) / E_TILE;
    integral_transform_kernel<<<blocks, THREADS, sizeof(Smem)>>>(
        pos, ei, W1, b1, Wh, bh, out, E);
}